// round 1
// baseline (speedup 1.0000x reference)
#include <cuda_runtime.h>

#define NNODES 50000
#define NEDGES 1600000
#define ETOT   (NEDGES + NNODES)
#define DH     128

// ---------------- scratch (static device globals; no allocations) ----------
__device__ float g_h[NNODES * DH];     // transformed features of current layer
__device__ float g_x[NNODES * DH];     // layer outputs
__device__ float g_ssrc[NNODES];
__device__ float g_sdst[NNODES];
__device__ int   g_rowptr[NNODES + 1];
__device__ int   g_cnt[NNODES];
__device__ int   g_srcs[ETOT];

// ---------------- CSR build ------------------------------------------------
__global__ void k_zero(int n) {
    int i = blockIdx.x * blockDim.x + threadIdx.x;
    if (i < n) g_cnt[i] = 0;
}

__global__ void k_hist(const int* __restrict__ ei, int E, int n) {
    int i = blockIdx.x * blockDim.x + threadIdx.x;
    if (i >= E + n) return;
    int d = (i < E) ? ei[E + i] : (i - E);   // row 1 of edge_index = dst; then self loops
    atomicAdd(&g_cnt[d], 1);
}

// single-block exclusive scan over g_cnt -> g_rowptr
__global__ void k_scan(int n) {
    __shared__ int sh[1024];
    __shared__ int soff;
    int t = threadIdx.x;
    if (t == 0) { soff = 0; g_rowptr[0] = 0; }
    __syncthreads();
    for (int base = 0; base < n; base += 1024) {
        int v = (base + t < n) ? g_cnt[base + t] : 0;
        sh[t] = v;
        __syncthreads();
        #pragma unroll
        for (int d = 1; d < 1024; d <<= 1) {
            int x = (t >= d) ? sh[t - d] : 0;
            __syncthreads();
            sh[t] += x;
            __syncthreads();
        }
        if (base + t < n) g_rowptr[base + t + 1] = soff + sh[t];
        __syncthreads();
        if (t == 0) soff += sh[1023];
        __syncthreads();
    }
}

__global__ void k_scatter(const int* __restrict__ ei, int E, int n) {
    int i = blockIdx.x * blockDim.x + threadIdx.x;
    if (i >= E + n) return;
    int s, d;
    if (i < E) { s = ei[i]; d = ei[E + i]; }
    else       { s = i - E; d = s; }
    int pos = g_rowptr[d] + atomicAdd(&g_cnt[d], 1);
    g_srcs[pos] = s;
}

// ---------------- GEMM: C[nrows, COLS] = A[nrows,128] @ B[128, COLS] (+bias)
template <int COLS>
__global__ void k_gemm(const float* __restrict__ A, const float* __restrict__ B,
                       const float* __restrict__ bias, float* __restrict__ C,
                       int nrows) {
    const int TPB = (COLS / 4) * 8;
    __shared__ float As[64 * 32];
    __shared__ float Bs[32 * COLS];
    int tx = threadIdx.x, ty = threadIdx.y;
    int tid = ty * (COLS / 4) + tx;
    int row0 = blockIdx.x * 64;

    float acc[8][4];
    #pragma unroll
    for (int r = 0; r < 8; r++)
        #pragma unroll
        for (int c = 0; c < 4; c++) acc[r][c] = 0.f;

    for (int k0 = 0; k0 < 128; k0 += 32) {
        // A tile: 64 rows x 32 k = 512 float4
        for (int idx4 = tid; idx4 < 512; idx4 += TPB) {
            int r = idx4 >> 3, kk4 = idx4 & 7;
            float4 v = make_float4(0.f, 0.f, 0.f, 0.f);
            int row = row0 + r;
            if (row < nrows) v = ((const float4*)A)[row * 32 + (k0 >> 2) + kk4];
            ((float4*)As)[r * 8 + kk4] = v;
        }
        // B tile: 32 k x COLS
        const int B4 = 32 * COLS / 4;
        for (int idx4 = tid; idx4 < B4; idx4 += TPB) {
            int kk = idx4 / (COLS / 4), c4 = idx4 % (COLS / 4);
            ((float4*)Bs)[idx4] = ((const float4*)B)[(k0 + kk) * (COLS / 4) + c4];
        }
        __syncthreads();
        #pragma unroll
        for (int kk = 0; kk < 32; kk++) {
            float4 b = ((float4*)Bs)[kk * (COLS / 4) + tx];
            #pragma unroll
            for (int r = 0; r < 8; r++) {
                float a = As[(ty * 8 + r) * 32 + kk];
                acc[r][0] += a * b.x;
                acc[r][1] += a * b.y;
                acc[r][2] += a * b.z;
                acc[r][3] += a * b.w;
            }
        }
        __syncthreads();
    }
    float4 bb = make_float4(0.f, 0.f, 0.f, 0.f);
    if (bias) bb = ((const float4*)bias)[tx];
    #pragma unroll
    for (int r = 0; r < 8; r++) {
        int row = row0 + ty * 8 + r;
        if (row < nrows) {
            float4 o = make_float4(acc[r][0] + bb.x, acc[r][1] + bb.y,
                                   acc[r][2] + bb.z, acc[r][3] + bb.w);
            ((float4*)C)[row * (COLS / 4) + tx] = o;
        }
    }
}

// ---------------- per-node attention dot products --------------------------
__global__ void k_svec(const float* __restrict__ h, const float* __restrict__ asrc,
                       const float* __restrict__ adst, int n) {
    int node = blockIdx.x * (blockDim.x >> 5) + (threadIdx.x >> 5);
    if (node >= n) return;
    int lane = threadIdx.x & 31;
    float4 hv = ((const float4*)h)[node * 32 + lane];
    float4 a = ((const float4*)asrc)[lane];
    float4 b = ((const float4*)adst)[lane];
    float s1 = hv.x * a.x + hv.y * a.y + hv.z * a.z + hv.w * a.w;
    float s2 = hv.x * b.x + hv.y * b.y + hv.z * b.z + hv.w * b.w;
    #pragma unroll
    for (int o = 16; o > 0; o >>= 1) {
        s1 += __shfl_xor_sync(0xffffffffu, s1, o);
        s2 += __shfl_xor_sync(0xffffffffu, s2, o);
    }
    if (lane == 0) { g_ssrc[node] = s1; g_sdst[node] = s2; }
}

// ---------------- GAT aggregation: one warp per dst node -------------------
__global__ void k_agg(const float* __restrict__ h, const float* __restrict__ bias,
                      float* __restrict__ out, int n, int do_relu) {
    int node = blockIdx.x * (blockDim.x >> 5) + (threadIdx.x >> 5);
    if (node >= n) return;
    int lane = threadIdx.x & 31;
    int beg = g_rowptr[node], end = g_rowptr[node + 1];
    float sd = g_sdst[node];

    // pass 1: max logit (all logits >= 0 after relu; every node has self-loop)
    float m = 0.f;
    for (int j = beg + lane; j < end; j += 32) {
        float e = fmaxf(g_ssrc[g_srcs[j]] + sd, 0.f);
        m = fmaxf(m, e);
    }
    #pragma unroll
    for (int o = 16; o > 0; o >>= 1)
        m = fmaxf(m, __shfl_xor_sync(0xffffffffu, m, o));

    // pass 2: fused exp-sum + weighted feature gather
    float4 acc = make_float4(0.f, 0.f, 0.f, 0.f);
    float dsum = 0.f;
    const float4* h4 = (const float4*)h;
    for (int base = beg; base < end; base += 32) {
        int j = base + lane;
        int sj = 0;
        float w = 0.f;
        if (j < end) {
            sj = g_srcs[j];
            float e = fmaxf(g_ssrc[sj] + sd, 0.f);
            w = __expf(e - m);
            dsum += w;
        }
        int cnt = min(32, end - base);
        for (int t = 0; t < cnt; t++) {
            int s = __shfl_sync(0xffffffffu, sj, t);
            float wt = __shfl_sync(0xffffffffu, w, t);
            float4 hv = h4[s * 32 + lane];
            acc.x += wt * hv.x;
            acc.y += wt * hv.y;
            acc.z += wt * hv.z;
            acc.w += wt * hv.w;
        }
    }
    #pragma unroll
    for (int o = 16; o > 0; o >>= 1)
        dsum += __shfl_xor_sync(0xffffffffu, dsum, o);

    float inv = 1.f / dsum;
    float4 bb = ((const float4*)bias)[lane];
    float4 r = make_float4(acc.x * inv + bb.x, acc.y * inv + bb.y,
                           acc.z * inv + bb.z, acc.w * inv + bb.w);
    if (do_relu) {
        r.x = fmaxf(r.x, 0.f); r.y = fmaxf(r.y, 0.f);
        r.z = fmaxf(r.z, 0.f); r.w = fmaxf(r.w, 0.f);
    }
    ((float4*)out)[node * 32 + lane] = r;
}

// ---------------- launch ----------------------------------------------------
extern "C" void kernel_launch(void* const* d_in, const int* in_sizes, int n_in,
                              void* d_out, int out_size) {
    const float* node_x = (const float*)d_in[0];
    const int*   ei     = (const int*)d_in[1];
    const float* W1  = (const float*)d_in[2];
    const float* as1 = (const float*)d_in[3];
    const float* ad1 = (const float*)d_in[4];
    const float* b1  = (const float*)d_in[5];
    const float* W2  = (const float*)d_in[6];
    const float* as2 = (const float*)d_in[7];
    const float* ad2 = (const float*)d_in[8];
    const float* b2  = (const float*)d_in[9];
    const float* Wo  = (const float*)d_in[10];
    const float* bo  = (const float*)d_in[11];
    float* out = (float*)d_out;

    int n = in_sizes[0] / 128;
    int E = in_sizes[1] / 2;
    int tot = E + n;

    float *hbuf, *xbuf;
    cudaGetSymbolAddress((void**)&hbuf, g_h);
    cudaGetSymbolAddress((void**)&xbuf, g_x);

    // CSR build (shared by both layers)
    k_zero<<<(n + 255) / 256, 256>>>(n);
    k_hist<<<(tot + 255) / 256, 256>>>(ei, E, n);
    k_scan<<<1, 1024>>>(n);
    k_zero<<<(n + 255) / 256, 256>>>(n);
    k_scatter<<<(tot + 255) / 256, 256>>>(ei, E, n);

    int gblocks = (n + 63) / 64;
    int wblocks = (n + 7) / 8;

    // layer 1
    k_gemm<128><<<gblocks, dim3(32, 8)>>>(node_x, W1, nullptr, hbuf, n);
    k_svec<<<wblocks, 256>>>(hbuf, as1, ad1, n);
    k_agg<<<wblocks, 256>>>(hbuf, b1, xbuf, n, 1);

    // layer 2
    k_gemm<128><<<gblocks, dim3(32, 8)>>>(xbuf, W2, nullptr, hbuf, n);
    k_svec<<<wblocks, 256>>>(hbuf, as2, ad2, n);
    k_agg<<<wblocks, 256>>>(hbuf, b2, xbuf, n, 0);

    // output linear
    k_gemm<64><<<gblocks, dim3(16, 8)>>>(xbuf, Wo, bo, out, n);
}

// round 2
// speedup vs baseline: 1.3885x; 1.3885x over previous
#include <cuda_runtime.h>

#define NNODES 50000
#define NEDGES 1600000
#define ETOT   (NEDGES + NNODES)
#define DH     128

// ---------------- scratch (static device globals; no allocations) ----------
__device__ float g_h[NNODES * DH];
__device__ float g_x[NNODES * DH];
__device__ float g_ssrc[NNODES];
__device__ float g_sdst[NNODES];
__device__ int   g_rowptr[NNODES + 1];
__device__ int   g_cnt[NNODES];        // histogram, then scatter cursor
__device__ int   g_bsum[260];          // block sums for scan
__device__ int   g_srcs[ETOT];

// ---------------- helpers ---------------------------------------------------
__device__ __forceinline__ unsigned long long f32x2_dup(float x) {
    unsigned long long r;
    unsigned u = __float_as_uint(x);
    asm("mov.b64 %0, {%1, %1};" : "=l"(r) : "r"(u));
    return r;
}
__device__ __forceinline__ void fma2(unsigned long long& acc,
                                     unsigned long long a, unsigned long long b) {
    asm("fma.rn.f32x2 %0, %1, %2, %0;" : "+l"(acc) : "l"(a), "l"(b));
}
__device__ __forceinline__ float f2lo(unsigned long long v) {
    return __uint_as_float((unsigned)v);
}
__device__ __forceinline__ float f2hi(unsigned long long v) {
    return __uint_as_float((unsigned)(v >> 32));
}

// ---------------- CSR build ------------------------------------------------
__global__ void k_zero(int n) {
    int i = blockIdx.x * blockDim.x + threadIdx.x;
    if (i < n) g_cnt[i] = 0;
}

__global__ void k_hist(const int* __restrict__ ei, int E, int n) {
    int i = blockIdx.x * blockDim.x + threadIdx.x;
    if (i >= E + n) return;
    int d = (i < E) ? ei[E + i] : (i - E);
    atomicAdd(&g_cnt[d], 1);
}

// phase 1: per-block exclusive scan of 256 counts; partial -> rowptr, sum -> bsum
__global__ void k_scan1(int n) {
    __shared__ int wsum[8];
    int t = threadIdx.x, lane = t & 31, w = t >> 5;
    int i = blockIdx.x * 256 + t;
    int v = (i < n) ? g_cnt[i] : 0;
    int x = v;
    #pragma unroll
    for (int o = 1; o < 32; o <<= 1) {
        int y = __shfl_up_sync(0xffffffffu, x, o);
        if (lane >= o) x += y;
    }
    if (lane == 31) wsum[w] = x;
    __syncthreads();
    if (w == 0) {
        int s = (lane < 8) ? wsum[lane] : 0;
        #pragma unroll
        for (int o = 1; o < 8; o <<= 1) {
            int y = __shfl_up_sync(0xffffffffu, s, o);
            if (lane >= o) s += y;
        }
        if (lane < 8) wsum[lane] = s;   // inclusive warp-sum scan
    }
    __syncthreads();
    int woff = (w == 0) ? 0 : wsum[w - 1];
    if (i < n) g_rowptr[i] = woff + x - v;   // exclusive within block
    if (t == 255) g_bsum[blockIdx.x] = wsum[7];
}

// phase 2: single warp exclusive-scans the block sums
__global__ void k_scan2(int nb) {
    int lane = threadIdx.x;
    int carry = 0;
    for (int base = 0; base < nb; base += 32) {
        int v = (base + lane < nb) ? g_bsum[base + lane] : 0;
        int x = v;
        #pragma unroll
        for (int o = 1; o < 32; o <<= 1) {
            int y = __shfl_up_sync(0xffffffffu, x, o);
            if (lane >= o) x += y;
        }
        if (base + lane < nb) g_bsum[base + lane] = carry + x - v;
        carry += __shfl_sync(0xffffffffu, x, 31);
    }
    if (lane == 0) g_bsum[nb] = carry;
}

// phase 3: add block offsets; seed scatter cursor; write rowptr[n]
__global__ void k_scan3(int n, int nb) {
    int i = blockIdx.x * 256 + threadIdx.x;
    if (i < n) {
        int v = g_rowptr[i] + g_bsum[blockIdx.x];
        g_rowptr[i] = v;
        g_cnt[i] = v;  // cursor
    }
    if (i == 0) g_rowptr[n] = g_bsum[nb];
}

__global__ void k_scatter(const int* __restrict__ ei, int E, int n) {
    int i = blockIdx.x * blockDim.x + threadIdx.x;
    if (i >= E + n) return;
    int s, d;
    if (i < E) { s = ei[i]; d = ei[E + i]; }
    else       { s = i - E; d = s; }
    int pos = atomicAdd(&g_cnt[d], 1);
    g_srcs[pos] = s;
}

// ---------------- GEMM (f32x2): C[nrows,COLS] = A[nrows,128] @ B[128,COLS] --
// Row-paired accumulators; optional fused attention-dot epilogue (SVEC).
template <int COLS, bool SVEC>
__global__ void k_gemm2(const float* __restrict__ A, const float* __restrict__ B,
                        const float* __restrict__ bias, float* __restrict__ C,
                        const float* __restrict__ asrc, const float* __restrict__ adst,
                        int nrows) {
    const int TPB = (COLS / 4) * 8;
    __shared__ __align__(16) float As[32][66];     // [k][row], pad keeps 8B align
    __shared__ __align__(16) float Bs[32 * COLS];  // [k][col]
    int tx = threadIdx.x, ty = threadIdx.y;
    int tid = ty * (COLS / 4) + tx;
    int row0 = blockIdx.x * 64;

    unsigned long long acc[4][4];   // [row-pair][col] ; lo = even row, hi = odd row
    #pragma unroll
    for (int rp = 0; rp < 4; rp++)
        #pragma unroll
        for (int c = 0; c < 4; c++) acc[rp][c] = 0ULL;

    for (int k0 = 0; k0 < 128; k0 += 32) {
        // A tile transposed: 64 rows x 32 k
        for (int idx = tid; idx < 512; idx += TPB) {
            int r = idx >> 3, kk4 = idx & 7;
            float4 v = make_float4(0.f, 0.f, 0.f, 0.f);
            if (row0 + r < nrows)
                v = ((const float4*)A)[(row0 + r) * 32 + (k0 >> 2) + kk4];
            As[kk4 * 4 + 0][r] = v.x;
            As[kk4 * 4 + 1][r] = v.y;
            As[kk4 * 4 + 2][r] = v.z;
            As[kk4 * 4 + 3][r] = v.w;
        }
        // B tile: 32 k x COLS
        for (int idx = tid; idx < 32 * COLS / 4; idx += TPB)
            ((float4*)Bs)[idx] =
                ((const float4*)B)[(k0 + (idx / (COLS / 4))) * (COLS / 4) + (idx % (COLS / 4))];
        __syncthreads();

        #pragma unroll
        for (int kk = 0; kk < 32; kk++) {
            unsigned long long ap[4];
            #pragma unroll
            for (int rp = 0; rp < 4; rp++)
                ap[rp] = *(const unsigned long long*)&As[kk][ty * 8 + 2 * rp];
            float4 b = ((const float4*)Bs)[kk * (COLS / 4) + tx];
            unsigned long long bp[4];
            bp[0] = f32x2_dup(b.x); bp[1] = f32x2_dup(b.y);
            bp[2] = f32x2_dup(b.z); bp[3] = f32x2_dup(b.w);
            #pragma unroll
            for (int rp = 0; rp < 4; rp++) {
                fma2(acc[rp][0], ap[rp], bp[0]);
                fma2(acc[rp][1], ap[rp], bp[1]);
                fma2(acc[rp][2], ap[rp], bp[2]);
                fma2(acc[rp][3], ap[rp], bp[3]);
            }
        }
        __syncthreads();
    }

    float4 bb = make_float4(0.f, 0.f, 0.f, 0.f);
    if (bias) bb = ((const float4*)bias)[tx];
    float4 va, vd;
    if (SVEC) {
        va = ((const float4*)asrc)[tx];
        vd = ((const float4*)adst)[tx];
    }

    #pragma unroll
    for (int rp = 0; rp < 4; rp++) {
        float l0 = f2lo(acc[rp][0]), l1 = f2lo(acc[rp][1]),
              l2 = f2lo(acc[rp][2]), l3 = f2lo(acc[rp][3]);
        float h0 = f2hi(acc[rp][0]), h1 = f2hi(acc[rp][1]),
              h2 = f2hi(acc[rp][2]), h3 = f2hi(acc[rp][3]);
        int r0 = row0 + ty * 8 + 2 * rp, r1 = r0 + 1;
        if (r0 < nrows)
            ((float4*)C)[r0 * (COLS / 4) + tx] =
                make_float4(l0 + bb.x, l1 + bb.y, l2 + bb.z, l3 + bb.w);
        if (r1 < nrows)
            ((float4*)C)[r1 * (COLS / 4) + tx] =
                make_float4(h0 + bb.x, h1 + bb.y, h2 + bb.z, h3 + bb.w);
        if (SVEC) {
            // warp = full 32 tx lanes covering all 128 cols (COLS==128 only)
            float ss0 = l0 * va.x + l1 * va.y + l2 * va.z + l3 * va.w;
            float sd0 = l0 * vd.x + l1 * vd.y + l2 * vd.z + l3 * vd.w;
            float ss1 = h0 * va.x + h1 * va.y + h2 * va.z + h3 * va.w;
            float sd1 = h0 * vd.x + h1 * vd.y + h2 * vd.z + h3 * vd.w;
            #pragma unroll
            for (int o = 16; o > 0; o >>= 1) {
                ss0 += __shfl_xor_sync(0xffffffffu, ss0, o);
                sd0 += __shfl_xor_sync(0xffffffffu, sd0, o);
                ss1 += __shfl_xor_sync(0xffffffffu, ss1, o);
                sd1 += __shfl_xor_sync(0xffffffffu, sd1, o);
            }
            if (tx == 0) {
                if (r0 < nrows) { g_ssrc[r0] = ss0; g_sdst[r0] = sd0; }
                if (r1 < nrows) { g_ssrc[r1] = ss1; g_sdst[r1] = sd1; }
            }
        }
    }
}

// ---------------- GAT aggregation: one warp per dst node -------------------
__global__ void k_agg(const float* __restrict__ h, const float* __restrict__ bias,
                      float* __restrict__ out, int n, int do_relu) {
    int node = blockIdx.x * (blockDim.x >> 5) + (threadIdx.x >> 5);
    if (node >= n) return;
    int lane = threadIdx.x & 31;
    int beg = g_rowptr[node], end = g_rowptr[node + 1];
    float sd = g_sdst[node];

    float m = 0.f;
    for (int j = beg + lane; j < end; j += 32) {
        float e = fmaxf(g_ssrc[g_srcs[j]] + sd, 0.f);
        m = fmaxf(m, e);
    }
    #pragma unroll
    for (int o = 16; o > 0; o >>= 1)
        m = fmaxf(m, __shfl_xor_sync(0xffffffffu, m, o));

    float4 acc = make_float4(0.f, 0.f, 0.f, 0.f);
    float dsum = 0.f;
    const float4* h4 = (const float4*)h;
    for (int base = beg; base < end; base += 32) {
        int j = base + lane;
        int sj = 0;
        float w = 0.f;
        if (j < end) {
            sj = g_srcs[j];
            float e = fmaxf(g_ssrc[sj] + sd, 0.f);
            w = __expf(e - m);
            dsum += w;
        }
        int cnt = min(32, end - base);
        for (int t = 0; t < cnt; t++) {
            int s = __shfl_sync(0xffffffffu, sj, t);
            float wt = __shfl_sync(0xffffffffu, w, t);
            float4 hv = h4[s * 32 + lane];
            acc.x += wt * hv.x;
            acc.y += wt * hv.y;
            acc.z += wt * hv.z;
            acc.w += wt * hv.w;
        }
    }
    #pragma unroll
    for (int o = 16; o > 0; o >>= 1)
        dsum += __shfl_xor_sync(0xffffffffu, dsum, o);

    float inv = 1.f / dsum;
    float4 bb = ((const float4*)bias)[lane];
    float4 r = make_float4(acc.x * inv + bb.x, acc.y * inv + bb.y,
                           acc.z * inv + bb.z, acc.w * inv + bb.w);
    if (do_relu) {
        r.x = fmaxf(r.x, 0.f); r.y = fmaxf(r.y, 0.f);
        r.z = fmaxf(r.z, 0.f); r.w = fmaxf(r.w, 0.f);
    }
    ((float4*)out)[node * 32 + lane] = r;
}

// ---------------- launch ----------------------------------------------------
extern "C" void kernel_launch(void* const* d_in, const int* in_sizes, int n_in,
                              void* d_out, int out_size) {
    const float* node_x = (const float*)d_in[0];
    const int*   ei     = (const int*)d_in[1];
    const float* W1  = (const float*)d_in[2];
    const float* as1 = (const float*)d_in[3];
    const float* ad1 = (const float*)d_in[4];
    const float* b1  = (const float*)d_in[5];
    const float* W2  = (const float*)d_in[6];
    const float* as2 = (const float*)d_in[7];
    const float* ad2 = (const float*)d_in[8];
    const float* b2  = (const float*)d_in[9];
    const float* Wo  = (const float*)d_in[10];
    const float* bo  = (const float*)d_in[11];
    float* out = (float*)d_out;

    int n = in_sizes[0] / 128;
    int E = in_sizes[1] / 2;
    int tot = E + n;
    int nb = (n + 255) / 256;

    float *hbuf, *xbuf;
    cudaGetSymbolAddress((void**)&hbuf, g_h);
    cudaGetSymbolAddress((void**)&xbuf, g_x);

    // CSR build (shared by both layers)
    k_zero<<<nb, 256>>>(n);
    k_hist<<<(tot + 255) / 256, 256>>>(ei, E, n);
    k_scan1<<<nb, 256>>>(n);
    k_scan2<<<1, 32>>>(nb);
    k_scan3<<<nb, 256>>>(n, nb);
    k_scatter<<<(tot + 255) / 256, 256>>>(ei, E, n);

    int gblocks = (n + 63) / 64;
    int wblocks = (n + 7) / 8;

    // layer 1 (GEMM + fused attention dots)
    k_gemm2<128, true><<<gblocks, dim3(32, 8)>>>(node_x, W1, nullptr, hbuf, as1, ad1, n);
    k_agg<<<wblocks, 256>>>(hbuf, b1, xbuf, n, 1);

    // layer 2
    k_gemm2<128, true><<<gblocks, dim3(32, 8)>>>(xbuf, W2, nullptr, hbuf, as2, ad2, n);
    k_agg<<<wblocks, 256>>>(hbuf, b2, xbuf, n, 0);

    // output linear
    k_gemm2<64, false><<<gblocks, dim3(16, 8)>>>(xbuf, Wo, bo, out, nullptr, nullptr, n);
}

// round 3
// speedup vs baseline: 1.4986x; 1.0793x over previous
#include <cuda_runtime.h>
#include <cuda_fp16.h>

#define NNODES 50000
#define NEDGES 1600000
#define ETOT   (NEDGES + NNODES)
#define DH     128

// ---------------- scratch (static device globals; no allocations) ----------
__device__ __half2 g_hh[NNODES * (DH / 2)];   // fp16 features (gather payload)
__device__ float   g_x[NNODES * DH];          // layer outputs (fp32)
__device__ float   g_ssrc[NNODES];
__device__ float   g_sdst[NNODES];
__device__ int     g_rowptr[NNODES + 1];
__device__ int     g_cnt[NNODES];             // histogram, then scatter cursor
__device__ int     g_bsum[260];
__device__ int     g_srcs[ETOT];

// ---------------- helpers ---------------------------------------------------
__device__ __forceinline__ unsigned long long f32x2_dup(float x) {
    unsigned long long r;
    unsigned u = __float_as_uint(x);
    asm("mov.b64 %0, {%1, %1};" : "=l"(r) : "r"(u));
    return r;
}
__device__ __forceinline__ void fma2(unsigned long long& acc,
                                     unsigned long long a, unsigned long long b) {
    asm("fma.rn.f32x2 %0, %1, %2, %0;" : "+l"(acc) : "l"(a), "l"(b));
}
__device__ __forceinline__ float f2lo(unsigned long long v) {
    return __uint_as_float((unsigned)v);
}
__device__ __forceinline__ float f2hi(unsigned long long v) {
    return __uint_as_float((unsigned)(v >> 32));
}

// ---------------- CSR build ------------------------------------------------
__global__ void k_zero(int n) {
    int i = blockIdx.x * blockDim.x + threadIdx.x;
    if (i < n) g_cnt[i] = 0;
}

__global__ void k_hist(const int* __restrict__ ei, int E, int n) {
    int i = blockIdx.x * blockDim.x + threadIdx.x;
    if (i >= E + n) return;
    int d = (i < E) ? ei[E + i] : (i - E);
    atomicAdd(&g_cnt[d], 1);
}

__global__ void k_scan1(int n) {
    __shared__ int wsum[8];
    int t = threadIdx.x, lane = t & 31, w = t >> 5;
    int i = blockIdx.x * 256 + t;
    int v = (i < n) ? g_cnt[i] : 0;
    int x = v;
    #pragma unroll
    for (int o = 1; o < 32; o <<= 1) {
        int y = __shfl_up_sync(0xffffffffu, x, o);
        if (lane >= o) x += y;
    }
    if (lane == 31) wsum[w] = x;
    __syncthreads();
    if (w == 0) {
        int s = (lane < 8) ? wsum[lane] : 0;
        #pragma unroll
        for (int o = 1; o < 8; o <<= 1) {
            int y = __shfl_up_sync(0xffffffffu, s, o);
            if (lane >= o) s += y;
        }
        if (lane < 8) wsum[lane] = s;
    }
    __syncthreads();
    int woff = (w == 0) ? 0 : wsum[w - 1];
    if (i < n) g_rowptr[i] = woff + x - v;
    if (t == 255) g_bsum[blockIdx.x] = wsum[7];
}

__global__ void k_scan2(int nb) {
    int lane = threadIdx.x;
    int carry = 0;
    for (int base = 0; base < nb; base += 32) {
        int v = (base + lane < nb) ? g_bsum[base + lane] : 0;
        int x = v;
        #pragma unroll
        for (int o = 1; o < 32; o <<= 1) {
            int y = __shfl_up_sync(0xffffffffu, x, o);
            if (lane >= o) x += y;
        }
        if (base + lane < nb) g_bsum[base + lane] = carry + x - v;
        carry += __shfl_sync(0xffffffffu, x, 31);
    }
    if (lane == 0) g_bsum[nb] = carry;
}

__global__ void k_scan3(int n, int nb) {
    int i = blockIdx.x * 256 + threadIdx.x;
    if (i < n) {
        int v = g_rowptr[i] + g_bsum[blockIdx.x];
        g_rowptr[i] = v;
        g_cnt[i] = v;
    }
    if (i == 0) g_rowptr[n] = g_bsum[nb];
}

__global__ void k_scatter(const int* __restrict__ ei, int E, int n) {
    int i = blockIdx.x * blockDim.x + threadIdx.x;
    if (i >= E + n) return;
    int s, d;
    if (i < E) { s = ei[i]; d = ei[E + i]; }
    else       { s = i - E; d = s; }
    int pos = atomicAdd(&g_cnt[d], 1);
    g_srcs[pos] = s;
}

// ---------------- GEMM (f32x2) ----------------------------------------------
// SVEC=true : layer GEMM. Writes fp16 features to g_hh and fused attention
//             dots (fp32) to g_ssrc/g_sdst. No bias.
// SVEC=false: output linear. Writes fp32 C with bias.
template <int COLS, bool SVEC>
__global__ void k_gemm2(const float* __restrict__ A, const float* __restrict__ B,
                        const float* __restrict__ bias, float* __restrict__ C,
                        const float* __restrict__ asrc, const float* __restrict__ adst,
                        int nrows) {
    const int TPB = (COLS / 4) * 8;
    __shared__ __align__(16) float As[32][66];
    __shared__ __align__(16) float Bs[32 * COLS];
    int tx = threadIdx.x, ty = threadIdx.y;
    int tid = ty * (COLS / 4) + tx;
    int row0 = blockIdx.x * 64;

    unsigned long long acc[4][4];
    #pragma unroll
    for (int rp = 0; rp < 4; rp++)
        #pragma unroll
        for (int c = 0; c < 4; c++) acc[rp][c] = 0ULL;

    for (int k0 = 0; k0 < 128; k0 += 32) {
        for (int idx = tid; idx < 512; idx += TPB) {
            int r = idx >> 3, kk4 = idx & 7;
            float4 v = make_float4(0.f, 0.f, 0.f, 0.f);
            if (row0 + r < nrows)
                v = ((const float4*)A)[(row0 + r) * 32 + (k0 >> 2) + kk4];
            As[kk4 * 4 + 0][r] = v.x;
            As[kk4 * 4 + 1][r] = v.y;
            As[kk4 * 4 + 2][r] = v.z;
            As[kk4 * 4 + 3][r] = v.w;
        }
        for (int idx = tid; idx < 32 * COLS / 4; idx += TPB)
            ((float4*)Bs)[idx] =
                ((const float4*)B)[(k0 + (idx / (COLS / 4))) * (COLS / 4) + (idx % (COLS / 4))];
        __syncthreads();

        #pragma unroll
        for (int kk = 0; kk < 32; kk++) {
            unsigned long long ap[4];
            #pragma unroll
            for (int rp = 0; rp < 4; rp++)
                ap[rp] = *(const unsigned long long*)&As[kk][ty * 8 + 2 * rp];
            float4 b = ((const float4*)Bs)[kk * (COLS / 4) + tx];
            unsigned long long bp[4];
            bp[0] = f32x2_dup(b.x); bp[1] = f32x2_dup(b.y);
            bp[2] = f32x2_dup(b.z); bp[3] = f32x2_dup(b.w);
            #pragma unroll
            for (int rp = 0; rp < 4; rp++) {
                fma2(acc[rp][0], ap[rp], bp[0]);
                fma2(acc[rp][1], ap[rp], bp[1]);
                fma2(acc[rp][2], ap[rp], bp[2]);
                fma2(acc[rp][3], ap[rp], bp[3]);
            }
        }
        __syncthreads();
    }

    float4 bb = make_float4(0.f, 0.f, 0.f, 0.f);
    if (!SVEC && bias) bb = ((const float4*)bias)[tx];
    float4 va, vd;
    if (SVEC) {
        va = ((const float4*)asrc)[tx];
        vd = ((const float4*)adst)[tx];
    }

    #pragma unroll
    for (int rp = 0; rp < 4; rp++) {
        float l0 = f2lo(acc[rp][0]), l1 = f2lo(acc[rp][1]),
              l2 = f2lo(acc[rp][2]), l3 = f2lo(acc[rp][3]);
        float h0 = f2hi(acc[rp][0]), h1 = f2hi(acc[rp][1]),
              h2 = f2hi(acc[rp][2]), h3 = f2hi(acc[rp][3]);
        int r0 = row0 + ty * 8 + 2 * rp, r1 = r0 + 1;
        if (SVEC) {
            // fp16 features
            if (r0 < nrows) {
                g_hh[r0 * 64 + 2 * tx]     = __floats2half2_rn(l0, l1);
                g_hh[r0 * 64 + 2 * tx + 1] = __floats2half2_rn(l2, l3);
            }
            if (r1 < nrows) {
                g_hh[r1 * 64 + 2 * tx]     = __floats2half2_rn(h0, h1);
                g_hh[r1 * 64 + 2 * tx + 1] = __floats2half2_rn(h2, h3);
            }
            float ss0 = l0 * va.x + l1 * va.y + l2 * va.z + l3 * va.w;
            float sd0 = l0 * vd.x + l1 * vd.y + l2 * vd.z + l3 * vd.w;
            float ss1 = h0 * va.x + h1 * va.y + h2 * va.z + h3 * va.w;
            float sd1 = h0 * vd.x + h1 * vd.y + h2 * vd.z + h3 * vd.w;
            #pragma unroll
            for (int o = 16; o > 0; o >>= 1) {
                ss0 += __shfl_xor_sync(0xffffffffu, ss0, o);
                sd0 += __shfl_xor_sync(0xffffffffu, sd0, o);
                ss1 += __shfl_xor_sync(0xffffffffu, ss1, o);
                sd1 += __shfl_xor_sync(0xffffffffu, sd1, o);
            }
            if (tx == 0) {
                if (r0 < nrows) { g_ssrc[r0] = ss0; g_sdst[r0] = sd0; }
                if (r1 < nrows) { g_ssrc[r1] = ss1; g_sdst[r1] = sd1; }
            }
        } else {
            if (r0 < nrows)
                ((float4*)C)[r0 * (COLS / 4) + tx] =
                    make_float4(l0 + bb.x, l1 + bb.y, l2 + bb.z, l3 + bb.w);
            if (r1 < nrows)
                ((float4*)C)[r1 * (COLS / 4) + tx] =
                    make_float4(h0 + bb.x, h1 + bb.y, h2 + bb.z, h3 + bb.w);
        }
    }
}

// ---------------- GAT aggregation: one warp per dst node, one-pass ----------
// Softmax is shift-invariant; logits bounded (|e| <= ||h||*||att|| ~ 11),
// so exp() without max subtraction is safe and saves a full edge sweep.
__global__ void k_agg(const float* __restrict__ bias,
                      float* __restrict__ out, int n, int do_relu) {
    int node = blockIdx.x * (blockDim.x >> 5) + (threadIdx.x >> 5);
    if (node >= n) return;
    int lane = threadIdx.x & 31;
    int beg = g_rowptr[node], end = g_rowptr[node + 1];
    float sd = g_sdst[node];

    float4 acc = make_float4(0.f, 0.f, 0.f, 0.f);
    float dsum = 0.f;
    const uint2* hh = (const uint2*)g_hh;   // 32 x uint2 per 128-half row
    for (int base = beg; base < end; base += 32) {
        int j = base + lane;
        int sj = 0;
        float w = 0.f;
        if (j < end) {
            sj = g_srcs[j];
            float e = fmaxf(g_ssrc[sj] + sd, 0.f);
            w = __expf(e);
            dsum += w;
        }
        int cnt = min(32, end - base);
        for (int t = 0; t < cnt; t++) {
            int s = __shfl_sync(0xffffffffu, sj, t);
            float wt = __shfl_sync(0xffffffffu, w, t);
            uint2 hv = hh[s * 32 + lane];
            float2 f01 = __half22float2(*(const __half2*)&hv.x);
            float2 f23 = __half22float2(*(const __half2*)&hv.y);
            acc.x += wt * f01.x;
            acc.y += wt * f01.y;
            acc.z += wt * f23.x;
            acc.w += wt * f23.y;
        }
    }
    #pragma unroll
    for (int o = 16; o > 0; o >>= 1)
        dsum += __shfl_xor_sync(0xffffffffu, dsum, o);

    float inv = 1.f / dsum;
    float4 bb = ((const float4*)bias)[lane];
    float4 r = make_float4(acc.x * inv + bb.x, acc.y * inv + bb.y,
                           acc.z * inv + bb.z, acc.w * inv + bb.w);
    if (do_relu) {
        r.x = fmaxf(r.x, 0.f); r.y = fmaxf(r.y, 0.f);
        r.z = fmaxf(r.z, 0.f); r.w = fmaxf(r.w, 0.f);
    }
    ((float4*)out)[node * 32 + lane] = r;
}

// ---------------- launch ----------------------------------------------------
extern "C" void kernel_launch(void* const* d_in, const int* in_sizes, int n_in,
                              void* d_out, int out_size) {
    const float* node_x = (const float*)d_in[0];
    const int*   ei     = (const int*)d_in[1];
    const float* W1  = (const float*)d_in[2];
    const float* as1 = (const float*)d_in[3];
    const float* ad1 = (const float*)d_in[4];
    const float* b1  = (const float*)d_in[5];
    const float* W2  = (const float*)d_in[6];
    const float* as2 = (const float*)d_in[7];
    const float* ad2 = (const float*)d_in[8];
    const float* b2  = (const float*)d_in[9];
    const float* Wo  = (const float*)d_in[10];
    const float* bo  = (const float*)d_in[11];
    float* out = (float*)d_out;

    int n = in_sizes[0] / 128;
    int E = in_sizes[1] / 2;
    int tot = E + n;
    int nb = (n + 255) / 256;

    float* xbuf;
    cudaGetSymbolAddress((void**)&xbuf, g_x);

    // CSR build (shared by both layers)
    k_zero<<<nb, 256>>>(n);
    k_hist<<<(tot + 255) / 256, 256>>>(ei, E, n);
    k_scan1<<<nb, 256>>>(n);
    k_scan2<<<1, 32>>>(nb);
    k_scan3<<<nb, 256>>>(n, nb);
    k_scatter<<<(tot + 255) / 256, 256>>>(ei, E, n);

    int gblocks = (n + 63) / 64;
    int wblocks = (n + 7) / 8;

    // layer 1 (GEMM -> fp16 features + fused attention dots)
    k_gemm2<128, true><<<gblocks, dim3(32, 8)>>>(node_x, W1, nullptr, nullptr, as1, ad1, n);
    k_agg<<<wblocks, 256>>>(b1, xbuf, n, 1);

    // layer 2
    k_gemm2<128, true><<<gblocks, dim3(32, 8)>>>(xbuf, W2, nullptr, nullptr, as2, ad2, n);
    k_agg<<<wblocks, 256>>>(b2, xbuf, n, 0);

    // output linear
    k_gemm2<64, false><<<gblocks, dim3(16, 8)>>>(xbuf, Wo, bo, out, nullptr, nullptr, n);
}

// round 4
// speedup vs baseline: 1.5580x; 1.0397x over previous
#include <cuda_runtime.h>
#include <cuda_fp16.h>

#define NNODES 50000
#define NEDGES 1600000
#define ETOT   (NEDGES + NNODES)
#define DH     128

// ---------------- scratch (static device globals; no allocations) ----------
__device__ __half2 g_hh[NNODES * (DH / 2)];   // fp16 features (gather payload)
__device__ float   g_x[NNODES * DH];          // layer outputs (fp32)
__device__ float   g_ssrc[NNODES];
__device__ float   g_sdst[NNODES];
__device__ int     g_rowptr[NNODES + 1];
__device__ int     g_cnt[NNODES];
__device__ int     g_bsum[260];
__device__ int     g_srcs[ETOT];
__device__ int     g_eoff[ETOT];              // per-edge within-dst offset

// ---------------- helpers ---------------------------------------------------
__device__ __forceinline__ unsigned long long f32x2_dup(float x) {
    unsigned long long r;
    unsigned u = __float_as_uint(x);
    asm("mov.b64 %0, {%1, %1};" : "=l"(r) : "r"(u));
    return r;
}
__device__ __forceinline__ void fma2(unsigned long long& acc,
                                     unsigned long long a, unsigned long long b) {
    asm("fma.rn.f32x2 %0, %1, %2, %0;" : "+l"(acc) : "l"(a), "l"(b));
}
__device__ __forceinline__ void add2(unsigned long long& acc, unsigned long long o) {
    asm("add.rn.f32x2 %0, %1, %2;" : "=l"(acc) : "l"(acc), "l"(o));
}
__device__ __forceinline__ unsigned long long pk2(float lo, float hi) {
    unsigned long long r;
    asm("mov.b64 %0, {%1, %2};" : "=l"(r) : "r"(__float_as_uint(lo)), "r"(__float_as_uint(hi)));
    return r;
}
__device__ __forceinline__ float f2lo(unsigned long long v) {
    return __uint_as_float((unsigned)v);
}
__device__ __forceinline__ float f2hi(unsigned long long v) {
    return __uint_as_float((unsigned)(v >> 32));
}

// ---------------- CSR build ------------------------------------------------
__global__ void k_zero(int n) {
    int i = blockIdx.x * blockDim.x + threadIdx.x;
    if (i < n) g_cnt[i] = 0;
}

// histogram; atomic return value = within-node slot -> g_eoff
__global__ void k_hist(const int* __restrict__ ei, int E, int n) {
    int i = blockIdx.x * blockDim.x + threadIdx.x;
    if (i >= E + n) return;
    int d = (i < E) ? ei[E + i] : (i - E);
    g_eoff[i] = atomicAdd(&g_cnt[d], 1);
}

__global__ void k_scan1(int n) {
    __shared__ int wsum[8];
    int t = threadIdx.x, lane = t & 31, w = t >> 5;
    int i = blockIdx.x * 256 + t;
    int v = (i < n) ? g_cnt[i] : 0;
    int x = v;
    #pragma unroll
    for (int o = 1; o < 32; o <<= 1) {
        int y = __shfl_up_sync(0xffffffffu, x, o);
        if (lane >= o) x += y;
    }
    if (lane == 31) wsum[w] = x;
    __syncthreads();
    if (w == 0) {
        int s = (lane < 8) ? wsum[lane] : 0;
        #pragma unroll
        for (int o = 1; o < 8; o <<= 1) {
            int y = __shfl_up_sync(0xffffffffu, s, o);
            if (lane >= o) s += y;
        }
        if (lane < 8) wsum[lane] = s;
    }
    __syncthreads();
    int woff = (w == 0) ? 0 : wsum[w - 1];
    if (i < n) g_rowptr[i] = woff + x - v;
    if (t == 255) g_bsum[blockIdx.x] = wsum[7];
}

__global__ void k_scan2(int nb) {
    int lane = threadIdx.x;
    int carry = 0;
    for (int base = 0; base < nb; base += 32) {
        int v = (base + lane < nb) ? g_bsum[base + lane] : 0;
        int x = v;
        #pragma unroll
        for (int o = 1; o < 32; o <<= 1) {
            int y = __shfl_up_sync(0xffffffffu, x, o);
            if (lane >= o) x += y;
        }
        if (base + lane < nb) g_bsum[base + lane] = carry + x - v;
        carry += __shfl_sync(0xffffffffu, x, 31);
    }
    if (lane == 0) g_bsum[nb] = carry;
}

__global__ void k_scan3(int n, int nb) {
    int i = blockIdx.x * 256 + threadIdx.x;
    if (i < n) g_rowptr[i] += g_bsum[blockIdx.x];
    if (i == 0) g_rowptr[n] = g_bsum[nb];
}

// atomic-free scatter
__global__ void k_scatter(const int* __restrict__ ei, int E, int n) {
    int i = blockIdx.x * blockDim.x + threadIdx.x;
    if (i >= E + n) return;
    int s, d;
    if (i < E) { s = ei[i]; d = ei[E + i]; }
    else       { s = i - E; d = s; }
    g_srcs[g_rowptr[d] + g_eoff[i]] = s;
}

// ---------------- GEMM (f32x2) ----------------------------------------------
template <int COLS, bool SVEC>
__global__ void k_gemm2(const float* __restrict__ A, const float* __restrict__ B,
                        const float* __restrict__ bias, float* __restrict__ C,
                        const float* __restrict__ asrc, const float* __restrict__ adst,
                        int nrows) {
    const int TPB = (COLS / 4) * 8;
    __shared__ __align__(16) float As[32][68];     // stride 272 B (16-aligned)
    __shared__ __align__(16) float Bs[32 * COLS];
    int tx = threadIdx.x, ty = threadIdx.y;
    int tid = ty * (COLS / 4) + tx;
    int row0 = blockIdx.x * 64;

    unsigned long long acc[4][4];
    #pragma unroll
    for (int rp = 0; rp < 4; rp++)
        #pragma unroll
        for (int c = 0; c < 4; c++) acc[rp][c] = 0ULL;

    for (int k0 = 0; k0 < 128; k0 += 32) {
        for (int idx = tid; idx < 512; idx += TPB) {
            int r = idx >> 3, kk4 = idx & 7;
            float4 v = make_float4(0.f, 0.f, 0.f, 0.f);
            if (row0 + r < nrows)
                v = ((const float4*)A)[(row0 + r) * 32 + (k0 >> 2) + kk4];
            As[kk4 * 4 + 0][r] = v.x;
            As[kk4 * 4 + 1][r] = v.y;
            As[kk4 * 4 + 2][r] = v.z;
            As[kk4 * 4 + 3][r] = v.w;
        }
        for (int idx = tid; idx < 32 * COLS / 4; idx += TPB)
            ((float4*)Bs)[idx] =
                ((const float4*)B)[(k0 + (idx / (COLS / 4))) * (COLS / 4) + (idx % (COLS / 4))];
        __syncthreads();

        #pragma unroll
        for (int kk = 0; kk < 32; kk++) {
            ulonglong2 v0 = *(const ulonglong2*)&As[kk][ty * 8];
            ulonglong2 v1 = *(const ulonglong2*)&As[kk][ty * 8 + 4];
            unsigned long long ap[4] = {v0.x, v0.y, v1.x, v1.y};
            float4 b = ((const float4*)Bs)[kk * (COLS / 4) + tx];
            unsigned long long bp[4];
            bp[0] = f32x2_dup(b.x); bp[1] = f32x2_dup(b.y);
            bp[2] = f32x2_dup(b.z); bp[3] = f32x2_dup(b.w);
            #pragma unroll
            for (int rp = 0; rp < 4; rp++) {
                fma2(acc[rp][0], ap[rp], bp[0]);
                fma2(acc[rp][1], ap[rp], bp[1]);
                fma2(acc[rp][2], ap[rp], bp[2]);
                fma2(acc[rp][3], ap[rp], bp[3]);
            }
        }
        __syncthreads();
    }

    float4 bb = make_float4(0.f, 0.f, 0.f, 0.f);
    if (!SVEC && bias) bb = ((const float4*)bias)[tx];
    float4 va, vd;
    if (SVEC) {
        va = ((const float4*)asrc)[tx];
        vd = ((const float4*)adst)[tx];
    }

    #pragma unroll
    for (int rp = 0; rp < 4; rp++) {
        float l0 = f2lo(acc[rp][0]), l1 = f2lo(acc[rp][1]),
              l2 = f2lo(acc[rp][2]), l3 = f2lo(acc[rp][3]);
        float h0 = f2hi(acc[rp][0]), h1 = f2hi(acc[rp][1]),
              h2 = f2hi(acc[rp][2]), h3 = f2hi(acc[rp][3]);
        int r0 = row0 + ty * 8 + 2 * rp, r1 = r0 + 1;
        if (SVEC) {
            if (r0 < nrows) {
                g_hh[r0 * 64 + 2 * tx]     = __floats2half2_rn(l0, l1);
                g_hh[r0 * 64 + 2 * tx + 1] = __floats2half2_rn(l2, l3);
            }
            if (r1 < nrows) {
                g_hh[r1 * 64 + 2 * tx]     = __floats2half2_rn(h0, h1);
                g_hh[r1 * 64 + 2 * tx + 1] = __floats2half2_rn(h2, h3);
            }
            float ss0 = l0 * va.x + l1 * va.y + l2 * va.z + l3 * va.w;
            float sd0 = l0 * vd.x + l1 * vd.y + l2 * vd.z + l3 * vd.w;
            float ss1 = h0 * va.x + h1 * va.y + h2 * va.z + h3 * va.w;
            float sd1 = h0 * vd.x + h1 * vd.y + h2 * vd.z + h3 * vd.w;
            #pragma unroll
            for (int o = 16; o > 0; o >>= 1) {
                ss0 += __shfl_xor_sync(0xffffffffu, ss0, o);
                sd0 += __shfl_xor_sync(0xffffffffu, sd0, o);
                ss1 += __shfl_xor_sync(0xffffffffu, ss1, o);
                sd1 += __shfl_xor_sync(0xffffffffu, sd1, o);
            }
            if (tx == 0) {
                if (r0 < nrows) { g_ssrc[r0] = ss0; g_sdst[r0] = sd0; }
                if (r1 < nrows) { g_ssrc[r1] = ss1; g_sdst[r1] = sd1; }
            }
        } else {
            if (r0 < nrows)
                ((float4*)C)[r0 * (COLS / 4) + tx] =
                    make_float4(l0 + bb.x, l1 + bb.y, l2 + bb.z, l3 + bb.w);
            if (r1 < nrows)
                ((float4*)C)[r1 * (COLS / 4) + tx] =
                    make_float4(h0 + bb.x, h1 + bb.y, h2 + bb.z, h3 + bb.w);
        }
    }
}

// ---------------- GAT aggregation -------------------------------------------
// warp per dst node; (src, w) staged in smem; 16-lane feature rows (LDG.128
// of 8 fp16), 2 edges per uniform inner iteration; fp32 accumulation via
// fma.rn.f32x2. One-pass softmax (logits bounded, shift-invariant).
__global__ void k_agg(const float* __restrict__ bias,
                      float* __restrict__ out, int n, int do_relu) {
    __shared__ uint2 stage[8][32];
    int wid = threadIdx.x >> 5;
    int node = blockIdx.x * 8 + wid;
    if (node >= n) return;
    int lane = threadIdx.x & 31;
    int sub = lane & 15, grp = lane >> 4;
    int beg = g_rowptr[node], end = g_rowptr[node + 1];
    float sd = g_sdst[node];

    unsigned long long acc[4] = {0ULL, 0ULL, 0ULL, 0ULL};
    float dsum = 0.f;
    const uint4* hh4 = (const uint4*)g_hh;   // 16 x uint4 per 128-half row

    for (int base = beg; base < end; base += 32) {
        int j = base + lane;
        int sj = 0;
        float w = 0.f;
        if (j < end) {
            sj = g_srcs[j];
            float e = fmaxf(g_ssrc[sj] + sd, 0.f);
            w = __expf(e);
            dsum += w;
        }
        stage[wid][lane] = make_uint2((unsigned)sj, __float_as_uint(w));
        __syncwarp();
        int cnt = min(32, end - base);
        int t = 0;
        #pragma unroll 4
        for (; t + 2 <= cnt; t += 2) {
            uint2 sw = stage[wid][t + grp];
            unsigned long long wd = f32x2_dup(__uint_as_float(sw.y));
            uint4 hv = hh4[(unsigned)sw.x * 16u + sub];
            float2 f0 = __half22float2(*(__half2*)&hv.x);
            float2 f1 = __half22float2(*(__half2*)&hv.y);
            float2 f2 = __half22float2(*(__half2*)&hv.z);
            float2 f3 = __half22float2(*(__half2*)&hv.w);
            fma2(acc[0], pk2(f0.x, f0.y), wd);
            fma2(acc[1], pk2(f1.x, f1.y), wd);
            fma2(acc[2], pk2(f2.x, f2.y), wd);
            fma2(acc[3], pk2(f3.x, f3.y), wd);
        }
        if (t < cnt && grp == 0) {   // odd tail edge: group 0 only
            uint2 sw = stage[wid][t];
            unsigned long long wd = f32x2_dup(__uint_as_float(sw.y));
            uint4 hv = hh4[(unsigned)sw.x * 16u + sub];
            float2 f0 = __half22float2(*(__half2*)&hv.x);
            float2 f1 = __half22float2(*(__half2*)&hv.y);
            float2 f2 = __half22float2(*(__half2*)&hv.z);
            float2 f3 = __half22float2(*(__half2*)&hv.w);
            fma2(acc[0], pk2(f0.x, f0.y), wd);
            fma2(acc[1], pk2(f1.x, f1.y), wd);
            fma2(acc[2], pk2(f2.x, f2.y), wd);
            fma2(acc[3], pk2(f3.x, f3.y), wd);
        }
        __syncwarp();
    }

    // combine the two 16-lane groups (both end with the full per-dim sum)
    #pragma unroll
    for (int i = 0; i < 4; i++) {
        unsigned long long o = __shfl_xor_sync(0xffffffffu, acc[i], 16);
        add2(acc[i], o);
    }
    #pragma unroll
    for (int o = 16; o > 0; o >>= 1)
        dsum += __shfl_xor_sync(0xffffffffu, dsum, o);

    float inv = 1.f / dsum;
    // lane (sub, grp) writes dims [8*sub + 4*grp .. +3]
    float o0, o1, o2, o3;
    if (grp == 0) {
        o0 = f2lo(acc[0]); o1 = f2hi(acc[0]);
        o2 = f2lo(acc[1]); o3 = f2hi(acc[1]);
    } else {
        o0 = f2lo(acc[2]); o1 = f2hi(acc[2]);
        o2 = f2lo(acc[3]); o3 = f2hi(acc[3]);
    }
    float4 bb = ((const float4*)bias)[sub * 2 + grp];
    float4 r = make_float4(o0 * inv + bb.x, o1 * inv + bb.y,
                           o2 * inv + bb.z, o3 * inv + bb.w);
    if (do_relu) {
        r.x = fmaxf(r.x, 0.f); r.y = fmaxf(r.y, 0.f);
        r.z = fmaxf(r.z, 0.f); r.w = fmaxf(r.w, 0.f);
    }
    ((float4*)out)[node * 32 + sub * 2 + grp] = r;
}

// ---------------- launch ----------------------------------------------------
extern "C" void kernel_launch(void* const* d_in, const int* in_sizes, int n_in,
                              void* d_out, int out_size) {
    const float* node_x = (const float*)d_in[0];
    const int*   ei     = (const int*)d_in[1];
    const float* W1  = (const float*)d_in[2];
    const float* as1 = (const float*)d_in[3];
    const float* ad1 = (const float*)d_in[4];
    const float* b1  = (const float*)d_in[5];
    const float* W2  = (const float*)d_in[6];
    const float* as2 = (const float*)d_in[7];
    const float* ad2 = (const float*)d_in[8];
    const float* b2  = (const float*)d_in[9];
    const float* Wo  = (const float*)d_in[10];
    const float* bo  = (const float*)d_in[11];
    float* out = (float*)d_out;

    int n = in_sizes[0] / 128;
    int E = in_sizes[1] / 2;
    int tot = E + n;
    int nb = (n + 255) / 256;

    float* xbuf;
    cudaGetSymbolAddress((void**)&xbuf, g_x);

    // CSR build (shared by both layers)
    k_zero<<<nb, 256>>>(n);
    k_hist<<<(tot + 255) / 256, 256>>>(ei, E, n);
    k_scan1<<<nb, 256>>>(n);
    k_scan2<<<1, 32>>>(nb);
    k_scan3<<<nb, 256>>>(n, nb);
    k_scatter<<<(tot + 255) / 256, 256>>>(ei, E, n);

    int gblocks = (n + 63) / 64;
    int wblocks = (n + 7) / 8;

    // layer 1
    k_gemm2<128, true><<<gblocks, dim3(32, 8)>>>(node_x, W1, nullptr, nullptr, as1, ad1, n);
    k_agg<<<wblocks, 256>>>(b1, xbuf, n, 1);

    // layer 2
    k_gemm2<128, true><<<gblocks, dim3(32, 8)>>>(xbuf, W2, nullptr, nullptr, as2, ad2, n);
    k_agg<<<wblocks, 256>>>(b2, xbuf, n, 0);

    // output linear
    k_gemm2<64, false><<<gblocks, dim3(16, 8)>>>(xbuf, Wo, bo, out, nullptr, nullptr, n);
}

// round 5
// speedup vs baseline: 1.8563x; 1.1914x over previous
#include <cuda_runtime.h>
#include <cuda_fp16.h>
#include <mma.h>
using namespace nvcuda;

#define NNODES 50000
#define NEDGES 1600000
#define ETOT   (NEDGES + NNODES)
#define DH     128

// ---------------- scratch (static device globals; no allocations) ----------
__device__ __half2 g_hh[NNODES * (DH / 2)];   // fp16 transformed features (gather payload)
__device__ __half2 g_xh[NNODES * (DH / 2)];   // fp16 layer outputs (GEMM A input)
__device__ float   g_ssrc[NNODES];
__device__ float   g_sdst[NNODES];
__device__ int     g_rowptr[NNODES + 1];
__device__ int     g_cnt[NNODES];
__device__ int     g_bsum[260];
__device__ int     g_srcs[ETOT];
__device__ int     g_eoff[ETOT];

// ---------------- helpers ---------------------------------------------------
__device__ __forceinline__ unsigned long long f32x2_dup(float x) {
    unsigned long long r;
    unsigned u = __float_as_uint(x);
    asm("mov.b64 %0, {%1, %1};" : "=l"(r) : "r"(u));
    return r;
}
__device__ __forceinline__ void fma2(unsigned long long& acc,
                                     unsigned long long a, unsigned long long b) {
    asm("fma.rn.f32x2 %0, %1, %2, %0;" : "+l"(acc) : "l"(a), "l"(b));
}
__device__ __forceinline__ void add2(unsigned long long& acc, unsigned long long o) {
    asm("add.rn.f32x2 %0, %1, %2;" : "=l"(acc) : "l"(acc), "l"(o));
}
__device__ __forceinline__ unsigned long long pk2(float lo, float hi) {
    unsigned long long r;
    asm("mov.b64 %0, {%1, %2};" : "=l"(r) : "r"(__float_as_uint(lo)), "r"(__float_as_uint(hi)));
    return r;
}
__device__ __forceinline__ float f2lo(unsigned long long v) {
    return __uint_as_float((unsigned)v);
}
__device__ __forceinline__ float f2hi(unsigned long long v) {
    return __uint_as_float((unsigned)(v >> 32));
}

// ---------------- CSR build ------------------------------------------------
__global__ void k_zero(int n) {
    int i = blockIdx.x * blockDim.x + threadIdx.x;
    if (i < n) g_cnt[i] = 0;
}

__global__ void k_hist(const int* __restrict__ ei, int E, int n) {
    int i = blockIdx.x * blockDim.x + threadIdx.x;
    if (i >= E + n) return;
    int d = (i < E) ? ei[E + i] : (i - E);
    g_eoff[i] = atomicAdd(&g_cnt[d], 1);
}

__global__ void k_scan1(int n) {
    __shared__ int wsum[8];
    int t = threadIdx.x, lane = t & 31, w = t >> 5;
    int i = blockIdx.x * 256 + t;
    int v = (i < n) ? g_cnt[i] : 0;
    int x = v;
    #pragma unroll
    for (int o = 1; o < 32; o <<= 1) {
        int y = __shfl_up_sync(0xffffffffu, x, o);
        if (lane >= o) x += y;
    }
    if (lane == 31) wsum[w] = x;
    __syncthreads();
    if (w == 0) {
        int s = (lane < 8) ? wsum[lane] : 0;
        #pragma unroll
        for (int o = 1; o < 8; o <<= 1) {
            int y = __shfl_up_sync(0xffffffffu, s, o);
            if (lane >= o) s += y;
        }
        if (lane < 8) wsum[lane] = s;
    }
    __syncthreads();
    int woff = (w == 0) ? 0 : wsum[w - 1];
    if (i < n) g_rowptr[i] = woff + x - v;
    if (t == 255) g_bsum[blockIdx.x] = wsum[7];
}

__global__ void k_scan2(int nb) {
    int lane = threadIdx.x;
    int carry = 0;
    for (int base = 0; base < nb; base += 32) {
        int v = (base + lane < nb) ? g_bsum[base + lane] : 0;
        int x = v;
        #pragma unroll
        for (int o = 1; o < 32; o <<= 1) {
            int y = __shfl_up_sync(0xffffffffu, x, o);
            if (lane >= o) x += y;
        }
        if (base + lane < nb) g_bsum[base + lane] = carry + x - v;
        carry += __shfl_sync(0xffffffffu, x, 31);
    }
    if (lane == 0) g_bsum[nb] = carry;
}

__global__ void k_scan3(int n, int nb) {
    int i = blockIdx.x * 256 + threadIdx.x;
    if (i < n) g_rowptr[i] += g_bsum[blockIdx.x];
    if (i == 0) g_rowptr[n] = g_bsum[nb];
}

__global__ void k_scatter(const int* __restrict__ ei, int E, int n) {
    int i = blockIdx.x * blockDim.x + threadIdx.x;
    if (i >= E + n) return;
    int s, d;
    if (i < E) { s = ei[i]; d = ei[E + i]; }
    else       { s = i - E; d = s; }
    g_srcs[g_rowptr[d] + g_eoff[i]] = s;
}

// ---------------- HMMA GEMM: C[nrows,COLS] = A[nrows,128] @ B[128,COLS] -----
// Block: 256 threads (8 warps), tile 128 rows x COLS. K staged in 64-slices.
// SVEC=true : writes fp16 features to g_hh + fused attention dots.
// SVEC=false: writes fp32 C with bias.
// A_HALF    : A is __half2 (g_xh) vs fp32 (converted while staging).
template <int COLS, bool SVEC, bool A_HALF>
__global__ void __launch_bounds__(256)
k_wgemm(const void* __restrict__ Aptr, const float* __restrict__ B,
        const float* __restrict__ bias, float* __restrict__ C,
        const float* __restrict__ asrc, const float* __restrict__ adst,
        int nrows) {
    const int NT = COLS / 16;
    const int BLD = COLS + 8;
    __shared__ __align__(16) __half As[128][72];    // 128 rows x 64 k
    __shared__ __align__(16) __half Bs[64][BLD];    // 64 k x COLS

    int tid = threadIdx.x;
    int w = tid >> 5, lane = tid & 31;
    int row0 = blockIdx.x * 128;

    wmma::fragment<wmma::accumulator, 16, 16, 16, float> acc[NT];
    #pragma unroll
    for (int nt = 0; nt < NT; nt++) wmma::fill_fragment(acc[nt], 0.f);

    for (int k0 = 0; k0 < 128; k0 += 64) {
        // --- stage A slice: rows 0..127, k = k0..k0+63 ---
        if (A_HALF) {
            const uint4* A16 = (const uint4*)Aptr;     // 16 uint4 per 128-half row
            for (int idx = tid; idx < 128 * 8; idx += 256) {
                int r = idx >> 3, q = idx & 7;
                uint4 v = make_uint4(0u, 0u, 0u, 0u);
                if (row0 + r < nrows) v = A16[(row0 + r) * 16 + (k0 >> 3) + q];
                *(uint4*)&As[r][q * 8] = v;
            }
        } else {
            const float4* A4 = (const float4*)Aptr;    // 32 float4 per 128-f32 row
            for (int idx = tid; idx < 128 * 16; idx += 256) {
                int r = idx >> 4, q = idx & 15;
                float4 v = make_float4(0.f, 0.f, 0.f, 0.f);
                if (row0 + r < nrows) v = A4[(row0 + r) * 32 + (k0 >> 2) + q];
                __half2 h0 = __floats2half2_rn(v.x, v.y);
                __half2 h1 = __floats2half2_rn(v.z, v.w);
                *(uint2*)&As[r][q * 4] = make_uint2(*(unsigned*)&h0, *(unsigned*)&h1);
            }
        }
        // --- stage B slice: k = k0..k0+63, all COLS ---
        {
            const float4* B4 = (const float4*)B;
            const int Q = COLS / 4;
            for (int idx = tid; idx < 64 * Q; idx += 256) {
                int kk = idx / Q, q = idx % Q;
                float4 v = B4[(k0 + kk) * Q + q];
                __half2 h0 = __floats2half2_rn(v.x, v.y);
                __half2 h1 = __floats2half2_rn(v.z, v.w);
                *(uint2*)&Bs[kk][q * 4] = make_uint2(*(unsigned*)&h0, *(unsigned*)&h1);
            }
        }
        __syncthreads();

        #pragma unroll
        for (int kk = 0; kk < 4; kk++) {
            wmma::fragment<wmma::matrix_a, 16, 16, 16, __half, wmma::row_major> af;
            wmma::load_matrix_sync(af, &As[w * 16][kk * 16], 72);
            #pragma unroll
            for (int nt = 0; nt < NT; nt++) {
                wmma::fragment<wmma::matrix_b, 16, 16, 16, __half, wmma::row_major> bf;
                wmma::load_matrix_sync(bf, &Bs[kk * 16][nt * 16], BLD);
                wmma::mma_sync(acc[nt], af, bf, acc[nt]);
            }
        }
        __syncthreads();
    }

    // ---- epilogue: per-warp scratch 16x20 floats (in As region) ----
    float* scr = ((float*)As) + w * 320;
    int r = lane & 15, hs = lane >> 4;
    int grow = row0 + w * 16 + r;
    float ss = 0.f, sd = 0.f;

    #pragma unroll
    for (int nt = 0; nt < NT; nt++) {
        wmma::store_matrix_sync(scr, acc[nt], 20, wmma::mem_row_major);
        __syncwarp();
        float v[8];
        #pragma unroll
        for (int j = 0; j < 8; j++) v[j] = scr[r * 20 + hs * 8 + j];
        __syncwarp();

        if (SVEC) {
            if (grow < nrows) {
                __half2 h0 = __floats2half2_rn(v[0], v[1]);
                __half2 h1 = __floats2half2_rn(v[2], v[3]);
                __half2 h2 = __floats2half2_rn(v[4], v[5]);
                __half2 h3 = __floats2half2_rn(v[6], v[7]);
                *(uint4*)&g_hh[grow * 64 + nt * 8 + hs * 4] =
                    make_uint4(*(unsigned*)&h0, *(unsigned*)&h1,
                               *(unsigned*)&h2, *(unsigned*)&h3);
            }
            float4 a0 = ((const float4*)asrc)[nt * 4 + hs * 2];
            float4 a1 = ((const float4*)asrc)[nt * 4 + hs * 2 + 1];
            float4 d0 = ((const float4*)adst)[nt * 4 + hs * 2];
            float4 d1 = ((const float4*)adst)[nt * 4 + hs * 2 + 1];
            ss += v[0] * a0.x + v[1] * a0.y + v[2] * a0.z + v[3] * a0.w
                + v[4] * a1.x + v[5] * a1.y + v[6] * a1.z + v[7] * a1.w;
            sd += v[0] * d0.x + v[1] * d0.y + v[2] * d0.z + v[3] * d0.w
                + v[4] * d1.x + v[5] * d1.y + v[6] * d1.z + v[7] * d1.w;
        } else {
            if (grow < nrows) {
                float4 b0 = ((const float4*)bias)[nt * 4 + hs * 2];
                float4 b1 = ((const float4*)bias)[nt * 4 + hs * 2 + 1];
                ((float4*)C)[grow * (COLS / 4) + nt * 4 + hs * 2] =
                    make_float4(v[0] + b0.x, v[1] + b0.y, v[2] + b0.z, v[3] + b0.w);
                ((float4*)C)[grow * (COLS / 4) + nt * 4 + hs * 2 + 1] =
                    make_float4(v[4] + b1.x, v[5] + b1.y, v[6] + b1.z, v[7] + b1.w);
            }
        }
    }
    if (SVEC) {
        ss += __shfl_xor_sync(0xffffffffu, ss, 16);
        sd += __shfl_xor_sync(0xffffffffu, sd, 16);
        if (hs == 0 && grow < nrows) { g_ssrc[grow] = ss; g_sdst[grow] = sd; }
    }
}

// ---------------- GAT aggregation -------------------------------------------
// warp per dst node; (src, w) staged in smem; 16-lane fp16 feature rows
// (LDG.128), 2 edges per inner iteration; fp32 f32x2 accumulation.
// One-pass softmax. Output written as fp16 to g_xh.
__global__ void k_agg(const float* __restrict__ bias, int n, int do_relu) {
    __shared__ uint2 stage[8][32];
    int wid = threadIdx.x >> 5;
    int node = blockIdx.x * 8 + wid;
    if (node >= n) return;
    int lane = threadIdx.x & 31;
    int sub = lane & 15, grp = lane >> 4;
    int beg = g_rowptr[node], end = g_rowptr[node + 1];
    float sd = g_sdst[node];

    unsigned long long acc[4] = {0ULL, 0ULL, 0ULL, 0ULL};
    float dsum = 0.f;
    const uint4* hh4 = (const uint4*)g_hh;

    for (int base = beg; base < end; base += 32) {
        int j = base + lane;
        int sj = 0;
        float w = 0.f;
        if (j < end) {
            sj = g_srcs[j];
            float e = fmaxf(g_ssrc[sj] + sd, 0.f);
            w = __expf(e);
            dsum += w;
        }
        stage[wid][lane] = make_uint2((unsigned)sj, __float_as_uint(w));
        __syncwarp();
        int cnt = min(32, end - base);
        int t = 0;
        #pragma unroll 4
        for (; t + 2 <= cnt; t += 2) {
            uint2 sw = stage[wid][t + grp];
            unsigned long long wd = f32x2_dup(__uint_as_float(sw.y));
            uint4 hv = hh4[(unsigned)sw.x * 16u + sub];
            float2 f0 = __half22float2(*(__half2*)&hv.x);
            float2 f1 = __half22float2(*(__half2*)&hv.y);
            float2 f2 = __half22float2(*(__half2*)&hv.z);
            float2 f3 = __half22float2(*(__half2*)&hv.w);
            fma2(acc[0], pk2(f0.x, f0.y), wd);
            fma2(acc[1], pk2(f1.x, f1.y), wd);
            fma2(acc[2], pk2(f2.x, f2.y), wd);
            fma2(acc[3], pk2(f3.x, f3.y), wd);
        }
        if (t < cnt && grp == 0) {
            uint2 sw = stage[wid][t];
            unsigned long long wd = f32x2_dup(__uint_as_float(sw.y));
            uint4 hv = hh4[(unsigned)sw.x * 16u + sub];
            float2 f0 = __half22float2(*(__half2*)&hv.x);
            float2 f1 = __half22float2(*(__half2*)&hv.y);
            float2 f2 = __half22float2(*(__half2*)&hv.z);
            float2 f3 = __half22float2(*(__half2*)&hv.w);
            fma2(acc[0], pk2(f0.x, f0.y), wd);
            fma2(acc[1], pk2(f1.x, f1.y), wd);
            fma2(acc[2], pk2(f2.x, f2.y), wd);
            fma2(acc[3], pk2(f3.x, f3.y), wd);
        }
        __syncwarp();
    }

    #pragma unroll
    for (int i = 0; i < 4; i++) {
        unsigned long long o = __shfl_xor_sync(0xffffffffu, acc[i], 16);
        add2(acc[i], o);
    }
    #pragma unroll
    for (int o = 16; o > 0; o >>= 1)
        dsum += __shfl_xor_sync(0xffffffffu, dsum, o);

    float inv = 1.f / dsum;
    float o0, o1, o2, o3;
    if (grp == 0) {
        o0 = f2lo(acc[0]); o1 = f2hi(acc[0]);
        o2 = f2lo(acc[1]); o3 = f2hi(acc[1]);
    } else {
        o0 = f2lo(acc[2]); o1 = f2hi(acc[2]);
        o2 = f2lo(acc[3]); o3 = f2hi(acc[3]);
    }
    float4 bb = ((const float4*)bias)[sub * 2 + grp];
    float rx = o0 * inv + bb.x, ry = o1 * inv + bb.y;
    float rz = o2 * inv + bb.z, rw = o3 * inv + bb.w;
    if (do_relu) {
        rx = fmaxf(rx, 0.f); ry = fmaxf(ry, 0.f);
        rz = fmaxf(rz, 0.f); rw = fmaxf(rw, 0.f);
    }
    __half2 ha = __floats2half2_rn(rx, ry);
    __half2 hb = __floats2half2_rn(rz, rw);
    *(uint2*)&g_xh[node * 64 + (sub * 2 + grp) * 2] =
        make_uint2(*(unsigned*)&ha, *(unsigned*)&hb);
}

// ---------------- launch ----------------------------------------------------
extern "C" void kernel_launch(void* const* d_in, const int* in_sizes, int n_in,
                              void* d_out, int out_size) {
    const float* node_x = (const float*)d_in[0];
    const int*   ei     = (const int*)d_in[1];
    const float* W1  = (const float*)d_in[2];
    const float* as1 = (const float*)d_in[3];
    const float* ad1 = (const float*)d_in[4];
    const float* b1  = (const float*)d_in[5];
    const float* W2  = (const float*)d_in[6];
    const float* as2 = (const float*)d_in[7];
    const float* ad2 = (const float*)d_in[8];
    const float* b2  = (const float*)d_in[9];
    const float* Wo  = (const float*)d_in[10];
    const float* bo  = (const float*)d_in[11];
    float* out = (float*)d_out;

    int n = in_sizes[0] / 128;
    int E = in_sizes[1] / 2;
    int tot = E + n;
    int nb = (n + 255) / 256;

    __half2* xh;
    cudaGetSymbolAddress((void**)&xh, g_xh);

    // CSR build (shared by both layers)
    k_zero<<<nb, 256>>>(n);
    k_hist<<<(tot + 255) / 256, 256>>>(ei, E, n);
    k_scan1<<<nb, 256>>>(n);
    k_scan2<<<1, 32>>>(nb);
    k_scan3<<<nb, 256>>>(n, nb);
    k_scatter<<<(tot + 255) / 256, 256>>>(ei, E, n);

    int gblocks = (n + 127) / 128;
    int wblocks = (n + 7) / 8;

    // layer 1: HMMA GEMM (fp32 A converted) + fused attention dots
    k_wgemm<128, true, false><<<gblocks, 256>>>(node_x, W1, nullptr, nullptr, as1, ad1, n);
    k_agg<<<wblocks, 256>>>(b1, n, 1);

    // layer 2: HMMA GEMM (fp16 A from agg)
    k_wgemm<128, true, true><<<gblocks, 256>>>(xh, W2, nullptr, nullptr, as2, ad2, n);
    k_agg<<<wblocks, 256>>>(b2, n, 0);

    // output linear: HMMA GEMM (fp16 A), fp32 out + bias
    k_wgemm<64, false, true><<<gblocks, 256>>>(xh, Wo, bo, out, nullptr, nullptr, n);
}